// round 15
// baseline (speedup 1.0000x reference)
#include <cuda_runtime.h>
#include <cuda_fp16.h>
#include <stdint.h>
#include <math.h>

#define B_ROWS 8192
#define D 512
#define NTHETA 608
#define NFORE (NTHETA - D)
#define NEXP 8
#define MAXP (B_ROWS * 2)
#define NCHUNK 8              // K=512 / 64
#define BM 128
#define BN 64
#define STG_BYTES 24576       // A 16K + B 8K
#define NSTAGE 3
#define GEMM_SMEM (1024 + NSTAGE * STG_BYTES)

// ---------------- device scratch ----------------
__device__ int   g_count[NEXP];
__device__ int   g_offset[NEXP];
__device__ int   g_cursor[NEXP];
__device__ int   g_token[MAXP];
__device__ int   g_slot[B_ROWS][2];
__device__ float g_gw[B_ROWS][2];

__device__ __half g_xh[B_ROWS * D];
__device__ __half g_W0h[NEXP * D * D];            // [e][n][k]  fp16
__device__ __half g_Wmh[3 * NEXP * D * D];        // [l*8+e][n][k]
__device__ __half g_Woh[NEXP * NTHETA * D];       // [e][n][k]
__device__ __half g_a0h[MAXP * D];
__device__ __half g_a1h[MAXP * D];
__device__ float g_theta[MAXP * NTHETA];

// ---------------- helpers ----------------
__device__ __forceinline__ uint32_t smem_u32(const void* p) {
    uint32_t a;
    asm("{ .reg .u64 t; cvta.to.shared.u64 t, %1; cvt.u32.u64 %0, t; }" : "=r"(a) : "l"(p));
    return a;
}
__device__ __forceinline__ void cpa16(uint32_t s, const void* g) {
    asm volatile("cp.async.cg.shared.global [%0], [%1], 16;" :: "r"(s), "l"(g) : "memory");
}
__device__ __forceinline__ void ldx4(uint32_t* r, uint32_t addr) {
    asm volatile("ldmatrix.sync.aligned.m8n8.x4.shared.b16 {%0,%1,%2,%3}, [%4];"
                 : "=r"(r[0]), "=r"(r[1]), "=r"(r[2]), "=r"(r[3]) : "r"(addr));
}
__device__ __forceinline__ void mma16816(float* d, const uint32_t* a, const uint32_t* b) {
    asm volatile(
        "mma.sync.aligned.m16n8k16.row.col.f32.f16.f16.f32 "
        "{%0,%1,%2,%3}, {%4,%5,%6,%7}, {%8,%9}, {%0,%1,%2,%3};"
        : "+f"(d[0]), "+f"(d[1]), "+f"(d[2]), "+f"(d[3])
        : "r"(a[0]), "r"(a[1]), "r"(a[2]), "r"(a[3]), "r"(b[0]), "r"(b[1]));
}

// ---------------- reset ----------------
__global__ void zero_kernel() {
    if (threadIdx.x < NEXP) g_count[threadIdx.x] = 0;
}

// ---------------- gate (also emits fp16 x) ----------------
__global__ void gate_kernel(const float* __restrict__ x,
                            const float* __restrict__ gamma,
                            const float* __restrict__ beta,
                            const float* __restrict__ Wg) {
    int row = blockIdx.x;
    const float* xr = x + (size_t)row * D;
    __shared__ float sx[D];
    __shared__ float ws[8], ws2[8];
    __shared__ float smu, srstd;
    __shared__ float logits[NEXP];

    int tid = threadIdx.x;
    float v0 = xr[tid], v1 = xr[tid + 256];
    sx[tid] = v0; sx[tid + 256] = v1;

    g_xh[(size_t)row * D + tid]       = __float2half(v0);
    g_xh[(size_t)row * D + tid + 256] = __float2half(v1);

    float s  = v0 + v1;
    float s2 = v0 * v0 + v1 * v1;
    #pragma unroll
    for (int o = 16; o; o >>= 1) {
        s  += __shfl_down_sync(0xFFFFFFFFu, s,  o);
        s2 += __shfl_down_sync(0xFFFFFFFFu, s2, o);
    }
    if ((tid & 31) == 0) { ws[tid >> 5] = s; ws2[tid >> 5] = s2; }
    __syncthreads();
    if (tid == 0) {
        float a = 0.f, b = 0.f;
        #pragma unroll
        for (int i = 0; i < 8; i++) { a += ws[i]; b += ws2[i]; }
        float mu  = a / (float)D;
        float var = b / (float)D - mu * mu;
        smu = mu;
        srstd = rsqrtf(var + 1e-5f);
    }
    __syncthreads();
    float mu = smu, rstd = srstd;

    int e = tid >> 5, lane = tid & 31;
    float acc = 0.f;
    for (int i = lane; i < D; i += 32) {
        float xn = (sx[i] - mu) * rstd * gamma[i] + beta[i];
        acc += xn * Wg[i * NEXP + e];
    }
    #pragma unroll
    for (int o = 16; o; o >>= 1) acc += __shfl_down_sync(0xFFFFFFFFu, acc, o);
    if (lane == 0) logits[e] = acc;
    __syncthreads();

    if (tid == 0) {
        int i0 = 0; float v0l = logits[0];
        #pragma unroll
        for (int i = 1; i < NEXP; i++) if (logits[i] > v0l) { v0l = logits[i]; i0 = i; }
        int i1 = -1; float v1l = -1e30f;
        #pragma unroll
        for (int i = 0; i < NEXP; i++) {
            if (i == i0) continue;
            if (logits[i] > v1l) { v1l = logits[i]; i1 = i; }
        }
        float e1 = __expf(v1l - v0l);
        float inv = 1.f / (1.f + e1);
        g_gw[row][0] = inv;
        g_gw[row][1] = e1 * inv;
        g_slot[row][0] = i0;
        g_slot[row][1] = i1;
        atomicAdd(&g_count[i0], 1);
        atomicAdd(&g_count[i1], 1);
    }
}

__global__ void prefix_kernel() {
    int off = 0;
    for (int e = 0; e < NEXP; e++) {
        g_offset[e] = off;
        g_cursor[e] = off;
        off += g_count[e];
    }
}

__global__ void assign_kernel() {
    int row = blockIdx.x * blockDim.x + threadIdx.x;
    if (row >= B_ROWS) return;
    #pragma unroll
    for (int k = 0; k < 2; k++) {
        int e = g_slot[row][k];
        int p = atomicAdd(&g_cursor[e], 1);
        g_token[p] = row;
        g_slot[row][k] = p;
    }
}

// ---------------- fused weight transpose+convert to fp16 -------------------
// z: 0..7 -> W0 (N=512), 8..31 -> Wmid (N=512), 32..39 -> Wout (N=608)
__global__ void wsplit_kernel(const float* __restrict__ W0,
                              const float* __restrict__ Wmid,
                              const float* __restrict__ Wout) {
    __shared__ float t[32][33];
    int z = blockIdx.z;
    const float* src;
    __half* dst;
    int N;
    if (z < 8)       { src = W0   + (size_t)z * D * D;        dst = g_W0h + (size_t)z * D * D;        N = D; }
    else if (z < 32) { src = Wmid + (size_t)(z - 8) * D * D;  dst = g_Wmh + (size_t)(z - 8) * D * D;  N = D; }
    else             { src = Wout + (size_t)(z - 32) * D * NTHETA;
                       dst = g_Woh + (size_t)(z - 32) * NTHETA * D; N = NTHETA; }

    int n0 = blockIdx.x * 32, k0 = blockIdx.y * 32;
    if (n0 >= N) return;
    int tx = threadIdx.x, ty = threadIdx.y;   // 32x8
    #pragma unroll
    for (int i = 0; i < 32; i += 8) {
        int k = k0 + ty + i, n = n0 + tx;
        t[ty + i][tx] = (n < N) ? src[(size_t)k * N + n] : 0.f;
    }
    __syncthreads();
    #pragma unroll
    for (int i = 0; i < 32; i += 8) {
        int n = n0 + ty + i, k = k0 + tx;
        if (n < N)
            dst[(size_t)n * D + k] = __float2half(t[tx][ty + i]);
    }
}

// ---------------- HMMA grouped GEMM: 128x64 tile, 3-stage, 1 barrier/chunk --
// asel: 0 = x (gather via g_token), 1 = a0, 2 = a1
// bsel: 0 = W0, 1..3 = Wmid layer, 4 = Wout
// csel: 0 = a0, 1 = a1, 2 = theta (fp32)
__global__ __launch_bounds__(256, 3)
void moe_gemm(int asel, int bsel, int csel, int Nfull, int relu) {
    extern __shared__ char smem[];
    int e = blockIdx.z;
    int cnt = g_count[e];
    int m0 = blockIdx.y * BM;
    if (m0 >= cnt) return;
    int n0 = blockIdx.x * BN;
    if (n0 >= Nfull) return;
    int base = g_offset[e];

    const __half *Ah;
    if (asel == 0)      Ah = g_xh;
    else if (asel == 1) Ah = g_a0h;
    else                Ah = g_a1h;
    const __half *Bh;
    if (bsel == 0)      Bh = g_W0h;
    else if (bsel <= 3) Bh = g_Wmh + (size_t)(bsel - 1) * NEXP * D * D;
    else                Bh = g_Woh;
    int gather = (asel == 0);
    int mode   = (csel == 2);
    __half* Ch = (csel == 0) ? g_a0h : g_a1h;

    uint32_t sb = smem_u32(smem);
    uint32_t tiles = (sb + 1023) & ~1023u;

    int tid = threadIdx.x;
    int wid = tid >> 5, lid = tid & 31;
    uint32_t m_warp = (uint32_t)((wid >> 1) * 32);   // 4 m-warps x 32 rows
    uint32_t n_warp = (uint32_t)((wid & 1) * 32);    // 2 n-warps x 32 cols

    // ---- A loader: one 64B half-row per thread (128 rows) ----
    int arow_l = tid >> 1;
    int ahalf  = (tid & 1) * 64;
    int am = m0 + arow_l; if (am >= cnt) am = 0;
    int arow_g = gather ? g_token[base + am] : (base + am);
    const char* pAh = (const char*)Ah + (size_t)arow_g * (D * 2) + ahalf;
    uint32_t axr = (uint32_t)(arow_l & 7) << 4;
    uint32_t aso = (uint32_t)arow_l * 128;

    // ---- B loader: one 32B quarter-row per thread (64 rows) ----
    int brow_l = tid >> 2;
    int bq     = (tid & 3) * 32;
    int bn = n0 + brow_l; if (bn >= Nfull) bn = 0;
    const char* pBh = (const char*)(Bh + (size_t)e * Nfull * D) + (size_t)bn * (D * 2) + bq;
    uint32_t bxr = (uint32_t)(brow_l & 7) << 4;
    uint32_t bso = (uint32_t)brow_l * 128;

    // ---- ldmatrix lane mapping ----
    int q = lid >> 3, r = lid & 7;
    uint32_t arow_q  = (uint32_t)((q & 1) * 8 + r);
    uint32_t abyte_q = (uint32_t)((q >> 1) * 16);
    uint32_t brow_q  = (uint32_t)((q >> 1) * 8 + r);
    uint32_t bbyte_q = (uint32_t)((q & 1) * 16);
    uint32_t lxor    = (uint32_t)r << 4;

    float acc[2][4][4];
    #pragma unroll
    for (int i = 0; i < 2; i++)
        #pragma unroll
        for (int j = 0; j < 4; j++)
            #pragma unroll
            for (int k = 0; k < 4; k++) acc[i][j][k] = 0.f;

    // ---- load chunk c into stage buffer c%3 ----
    auto load_chunk = [&](int c) {
        uint32_t st = tiles + (uint32_t)(c % NSTAGE) * STG_BYTES;
        size_t goff = (size_t)c * 128;
        #pragma unroll
        for (int i = 0; i < 4; i++) {
            uint32_t so = aso + (((uint32_t)(ahalf + i * 16)) ^ axr);
            cpa16(st + so, pAh + goff + i * 16);
        }
        #pragma unroll
        for (int i = 0; i < 2; i++) {
            uint32_t so = bso + (((uint32_t)(bq + i * 16)) ^ bxr);
            cpa16(st + 16384 + so, pBh + goff + i * 16);
        }
        asm volatile("cp.async.commit_group;" ::: "memory");
    };

    // ---- prologue: chunks 0,1 in flight ----
    load_chunk(0);
    load_chunk(1);

    #pragma unroll 1
    for (int c = 0; c < NCHUNK; c++) {
        // wait for chunk c (leave chunk c+1 outstanding if it exists)
        if (c < NCHUNK - 1) {
            asm volatile("cp.async.wait_group 1;" ::: "memory");
        } else {
            asm volatile("cp.async.wait_group 0;" ::: "memory");
        }
        // single barrier: data of chunk c visible to all; all warps done
        // reading buffer (c+2)%3 (last used for chunk c-1)
        __syncthreads();
        // prefetch chunk c+2 into buffer (c+2)%3 — now safe
        if (c + 2 < NCHUNK) load_chunk(c + 2);

        uint32_t st = tiles + (uint32_t)(c % NSTAGE) * STG_BYTES;
        uint32_t sAh = st, sBh = st + 16384;

        #pragma unroll
        for (int kk = 0; kk < 4; kk++) {
            uint32_t bh[8];
            #pragma unroll
            for (int g2 = 0; g2 < 2; g2++) {
                uint32_t ro = (n_warp + (uint32_t)(g2 * 16) + brow_q) * 128;
                uint32_t co = ((uint32_t)(kk * 32) + bbyte_q) ^ lxor;
                ldx4(bh + g2 * 4, sBh + ro + co);
            }
            #pragma unroll
            for (int mt = 0; mt < 2; mt++) {
                uint32_t ah[4];
                uint32_t ro = (m_warp + (uint32_t)(mt * 16) + arow_q) * 128;
                uint32_t co = ((uint32_t)(kk * 32) + abyte_q) ^ lxor;
                ldx4(ah, sAh + ro + co);
                #pragma unroll
                for (int nt = 0; nt < 4; nt++) {
                    const uint32_t* bp = bh + (nt >> 1) * 4 + (nt & 1) * 2;
                    mma16816(acc[mt][nt], ah, bp);
                }
            }
        }
    }

    // ---- epilogue ----
    int g = lid >> 2, tig = lid & 3;
    #pragma unroll
    for (int mt = 0; mt < 2; mt++) {
        #pragma unroll
        for (int half = 0; half < 2; half++) {
            int m = m0 + (int)m_warp + mt * 16 + g + half * 8;
            if (m >= cnt) continue;
            size_t orow = (size_t)(base + m);
            #pragma unroll
            for (int nt = 0; nt < 4; nt++) {
                int ncol = n0 + (int)n_warp + nt * 8 + tig * 2;
                float v0 = acc[mt][nt][half * 2 + 0];
                float v1 = acc[mt][nt][half * 2 + 1];
                if (mode == 0) {
                    if (relu) { v0 = fmaxf(v0, 0.f); v1 = fmaxf(v1, 0.f); }
                    __half2 hp; hp.x = __float2half(v0); hp.y = __float2half(v1);
                    *(__half2*)(Ch + orow * D + ncol) = hp;
                } else {
                    if (ncol < NTHETA) {
                        float2 fv; fv.x = v0; fv.y = v1;
                        *(float2*)(g_theta + orow * NTHETA + ncol) = fv;
                    }
                }
            }
        }
    }
}

// ---------------- combine ----------------
__global__ void combine_kernel(float* __restrict__ out) {
    int row = blockIdx.x;
    int p0 = g_slot[row][0], p1 = g_slot[row][1];
    float w0 = g_gw[row][0], w1 = g_gw[row][1];
    const float* t0 = g_theta + (size_t)p0 * NTHETA;
    const float* t1 = g_theta + (size_t)p1 * NTHETA;
    for (int t = threadIdx.x; t < NTHETA; t += blockDim.x) {
        float v = w0 * t0[t] + w1 * t1[t];
        if (t < D) out[(size_t)row * D + t] = v;
        else       out[(size_t)B_ROWS * D + (size_t)row * NFORE + (t - D)] = v;
    }
}

// ---------------- launch ----------------
extern "C" void kernel_launch(void* const* d_in, const int* in_sizes, int n_in,
                              void* d_out, int out_size) {
    const float* x     = (const float*)d_in[0];
    const float* gamma = (const float*)d_in[1];
    const float* beta  = (const float*)d_in[2];
    const float* Wg    = (const float*)d_in[3];
    const float* W0    = (const float*)d_in[4];
    const float* Wmid  = (const float*)d_in[5];
    const float* Wout  = (const float*)d_in[6];
    float* out = (float*)d_out;

    cudaFuncSetAttribute(moe_gemm, cudaFuncAttributeMaxDynamicSharedMemorySize, GEMM_SMEM);

    zero_kernel<<<1, 32>>>();
    gate_kernel<<<B_ROWS, 256>>>(x, gamma, beta, Wg);
    prefix_kernel<<<1, 1>>>();
    assign_kernel<<<B_ROWS / 256, 256>>>();

    wsplit_kernel<<<dim3(19, 16, 40), dim3(32, 8)>>>(W0, Wmid, Wout);

    dim3 blk(256);
    dim3 g512(8, 64, NEXP);    // BN=64 -> 8 n-tiles
    dim3 g608(10, 64, NEXP);   // 608 -> 10 n-tiles

    // asel, bsel, csel, Nfull, relu
    moe_gemm<<<g512, blk, GEMM_SMEM>>>(0, 0, 0, D, 0);       // x @ W0       -> a0
    moe_gemm<<<g512, blk, GEMM_SMEM>>>(1, 1, 1, D, 1);       // relu(a0@Wm0) -> a1
    moe_gemm<<<g512, blk, GEMM_SMEM>>>(2, 2, 0, D, 1);       // relu(a1@Wm1) -> a0
    moe_gemm<<<g512, blk, GEMM_SMEM>>>(1, 3, 1, D, 1);       // relu(a0@Wm2) -> a1
    moe_gemm<<<g608, blk, GEMM_SMEM>>>(2, 4, 2, NTHETA, 0);  // a1 @ Wout    -> theta

    combine_kernel<<<B_ROWS, 256>>>(out);
}